// round 11
// baseline (speedup 1.0000x reference)
#include <cuda_runtime.h>
#include <math.h>
#include <stdint.h>

#define S_LEN 2048
#define DM    2048
#define QH    32
#define KVH   8
#define DH    64
#define KV_W  (2 * KVH * DH)   // 1024

// ---------------- scratch (allocation-free: __device__ globals) ----------------
__device__ float g_Qf[S_LEN * DM];            // fp32 Q proj (pre-rope)
__device__ float g_KVf[S_LEN * KV_W];         // fp32 KV proj
__device__ uint2 g_xp[S_LEN * DM / 2];        // packed x
__device__ uint2 g_Wqp[DM * DM / 2];          // packed W_q
__device__ uint2 g_Wkvp[KV_W * DM / 2];       // packed W_kv
__device__ uint2 g_Wop[DM * DM / 2];          // packed W_out
__device__ uint2 g_Qp[S_LEN * DM / 2];        // packed rope'd scaled Q
__device__ uint2 g_Kp[S_LEN * KVH * DH / 2];  // packed rope'd K
__device__ uint2 g_Vtp[KVH * DH * S_LEN / 2]; // packed V^T (pairs along seq)
__device__ uint2 g_attnp[S_LEN * DM / 2];     // packed attention output

// ============================ helpers ====================================
__device__ __forceinline__ uint32_t smem_u32(const void* p) {
    uint32_t a;
    asm("{ .reg .u64 t; cvta.to.shared.u64 t, %1; cvt.u32.u64 %0, t; }" : "=r"(a) : "l"(p));
    return a;
}
#define CP_ASYNC16(dst, src) \
    asm volatile("cp.async.cg.shared.global [%0], [%1], 16;" :: "r"(dst), "l"(src))
#define CP_COMMIT() asm volatile("cp.async.commit_group;" ::: "memory")
#define CP_WAIT1()  asm volatile("cp.async.wait_group 1;" ::: "memory")

__device__ __forceinline__ uint32_t pack_bf16(float f1_hi, float f0_lo) {
    uint32_t d;
    asm("cvt.rn.bf16x2.f32 %0, %1, %2;" : "=r"(d) : "f"(f1_hi), "f"(f0_lo));
    return d;
}
// round-to-nearest hi/lo split of a pair: f = hi + lo, |lo| <= 2^-8 |f|
__device__ __forceinline__ void split2(float f0, float f1, uint32_t& h, uint32_t& l) {
    h = pack_bf16(f1, f0);
    float h0 = __uint_as_float(h << 16);
    float h1 = __uint_as_float(h & 0xFFFF0000u);
    l = pack_bf16(f1 - h1, f0 - h0);
}
__device__ __forceinline__ void mma_bf16(float* d,
                                         uint32_t a0, uint32_t a1, uint32_t a2, uint32_t a3,
                                         uint32_t b0, uint32_t b1) {
    asm volatile(
        "mma.sync.aligned.m16n8k16.row.col.f32.bf16.bf16.f32 "
        "{%0,%1,%2,%3}, {%4,%5,%6,%7}, {%8,%9}, {%0,%1,%2,%3};"
        : "+f"(d[0]), "+f"(d[1]), "+f"(d[2]), "+f"(d[3])
        : "r"(a0), "r"(a1), "r"(a2), "r"(a3), "r"(b0), "r"(b1));
}

// ==============================================================================
// pre-pack: fp32 pairs -> {hi bf16x2, lo bf16x2}
// ==============================================================================
__global__ void pack_pairs(const float2* __restrict__ in, uint2* __restrict__ out, int n2)
{
    int i = blockIdx.x * blockDim.x + threadIdx.x;
    if (i >= n2) return;
    float2 f = in[i];
    uint2 o;
    split2(f.x, f.y, o.x, o.y);
    out[i] = o;
}

// ==============================================================================
// 3xBF16 GEMM, packed operands, R8 tiling: C = A @ B^T + bias
// 128x128 CTA tile, BK=16 (=8 uint2/row), 128 threads (4 warps, 64x64 tiles).
// smem: 3 stages of A[128][8u2]+B[128][8u2], row stride 12 uint2 (96B,
// conflict-free: 12r+qc distinct mod 16 over half-warp).
// Mainloop: pure LDS.64 + HMMA — zero conversion ALU. occ 3.
// ==============================================================================
#define GST      12                    // uint2 per row (8 data + 4 pad)
#define GTILE_U  (128 * GST)           // 1536 uint2
#define GSTG_U   (2 * GTILE_U)         // A+B per stage
#define GNSTG    3
#define TG_SMEM  (GNSTG * GSTG_U * 8)  // 73728 B

__global__ __launch_bounds__(128, 3)
void tgemm_bf16p(const uint2* __restrict__ A, const uint2* __restrict__ B,
                 const float* __restrict__ bias, float* __restrict__ C,
                 int M, int N, int K)
{
    extern __shared__ uint2 smu[];
    const uint32_t smb = smem_u32(smu);

    const int tid  = threadIdx.x;
    const int wid  = tid >> 5;
    const int lane = tid & 31;
    const int qr   = lane >> 2;
    const int qc   = lane & 3;
    const int wm   = (wid & 1) * 64;
    const int wn   = (wid >> 1) * 64;
    const int brow = blockIdx.y * 128;
    const int bcol = blockIdx.x * 128;
    const int ldu  = K >> 1;

    // loader: thread owns A row tid and B row tid (64 B data each per stage)
    const uint2* Ag = A + (size_t)(brow + tid) * ldu;
    const uint2* Bg = B + (size_t)(bcol + tid) * ldu;
    const uint32_t dst_off = (uint32_t)tid * (GST * 8);

    const int NT = K >> 4;

    auto issue_stage = [&](int kt) {
        const uint32_t da = smb + (uint32_t)((kt % GNSTG) * GSTG_U) * 8 + dst_off;
        const uint32_t db = da + GTILE_U * 8;
        const uint2* sa = Ag + kt * 8;
        const uint2* sb = Bg + kt * 8;
#pragma unroll
        for (int j = 0; j < 4; j++) {
            CP_ASYNC16(da + 16 * j, sa + 2 * j);
            CP_ASYNC16(db + 16 * j, sb + 2 * j);
        }
    };

    float acc[4][8][4];
#pragma unroll
    for (int mt = 0; mt < 4; mt++)
#pragma unroll
        for (int nt = 0; nt < 8; nt++)
#pragma unroll
            for (int i = 0; i < 4; i++) acc[mt][nt][i] = 0.0f;

    issue_stage(0); CP_COMMIT();
    issue_stage(1); CP_COMMIT();

    for (int kt = 0; kt < NT; kt++) {
        CP_WAIT1();
        __syncthreads();

        if (kt + 2 < NT) issue_stage(kt + 2);
        CP_COMMIT();

        const uint2* As = smu + (kt % GNSTG) * GSTG_U;
        const uint2* Bs = As + GTILE_U;

        uint2 bf[8][2];
#pragma unroll
        for (int nt = 0; nt < 8; nt++) {
            const int o = (wn + nt * 8 + qr) * GST + qc;
            bf[nt][0] = Bs[o];
            bf[nt][1] = Bs[o + 4];
        }
#pragma unroll
        for (int mt = 0; mt < 4; mt++) {
            const int o = (wm + mt * 16 + qr) * GST + qc;
            uint2 a0 = As[o];
            uint2 a1 = As[o + 8 * GST];
            uint2 a2 = As[o + 4];
            uint2 a3 = As[o + 8 * GST + 4];
#pragma unroll
            for (int nt = 0; nt < 8; nt++) {
                mma_bf16(acc[mt][nt], a0.x, a1.x, a2.x, a3.x, bf[nt][0].x, bf[nt][1].x);
                mma_bf16(acc[mt][nt], a0.x, a1.x, a2.x, a3.x, bf[nt][0].y, bf[nt][1].y);
                mma_bf16(acc[mt][nt], a0.y, a1.y, a2.y, a3.y, bf[nt][0].x, bf[nt][1].x);
            }
        }
        __syncthreads();
    }

#pragma unroll
    for (int mt = 0; mt < 4; mt++) {
        const int row = brow + wm + mt * 16 + qr;
#pragma unroll
        for (int nt = 0; nt < 8; nt++) {
            const int col = bcol + wn + nt * 8 + qc * 2;
            const float b0 = bias[col], b1 = bias[col + 1];
            *(float2*)(C + (size_t)row * N + col) =
                make_float2(acc[mt][nt][0] + b0, acc[mt][nt][1] + b1);
            *(float2*)(C + (size_t)(row + 8) * N + col) =
                make_float2(acc[mt][nt][2] + b0, acc[mt][nt][3] + b1);
        }
    }
}

// ==============================================================================
// RoPE + scale + pack
// ==============================================================================
__global__ void ropepack_kernel(const float* __restrict__ X, uint2* __restrict__ out,
                                int H, int istride, int ostride, float scale)
{
    __shared__ float sfreq[32];
    if (threadIdx.x < 32)
        sfreq[threadIdx.x] = (float)pow(10000.0, -(double)threadIdx.x / 32.0);
    __syncthreads();

    int idx = blockIdx.x * blockDim.x + threadIdx.x;
    int total = S_LEN * H * (DH / 2);
    if (idx >= total) return;

    int j = idx & 31;
    int t = idx >> 5;
    int h = t % H;
    int s = t / H;

    float theta = (float)s * sfreq[j];
    float sn, cs;
    sincosf(theta, &sn, &cs);

    const float* p = X + (size_t)s * istride + h * DH + 2 * j;
    float x1 = p[0], x2 = p[1];
    float o1 = (x1 * cs - x2 * sn) * scale;
    float o2 = (x1 * sn + x2 * cs) * scale;
    uint2 o;
    split2(o1, o2, o.x, o.y);
    out[(size_t)s * ostride + h * (DH / 2) + j] = o;
}

// V^T pack: g_Vtp[hk*64+d][sp] = split(V[2sp][hk,d], V[2sp+1][hk,d])
__global__ void vtpack_kernel(const float* __restrict__ KV, uint2* __restrict__ Vt)
{
    int idx = blockIdx.x * blockDim.x + threadIdx.x;
    if (idx >= KVH * DH * (S_LEN / 2)) return;
    int sp = idx & (S_LEN / 2 - 1);
    int d  = (idx >> 10) & (DH - 1);
    int hk = idx >> 16;
    const float* base = KV + (size_t)(2 * sp) * KV_W + KVH * DH + hk * DH + d;
    float v0 = base[0];
    float v1 = base[KV_W];
    uint2 o;
    split2(v0, v1, o.x, o.y);
    Vt[idx] = o;
}

// ==============================================================================
// Flash attention: Q in registers (loaded once), P in registers (no smem
// round-trip), K/V packed in smem. 128 q-rows x head per block, 4 warps.
// ==============================================================================
#define AST 36                                   // uint2 row stride (4 mod 16)
#define OFF_K 0
#define OFF_V (64 * AST * 8)                     // 18432
#define FA_SMEM (2 * 64 * AST * 8)               // 36864

__global__ __launch_bounds__(128, 2)
void flash_attn_p(const uint2* __restrict__ Qp, const uint2* __restrict__ Kp,
                  const uint2* __restrict__ Vtp, uint2* __restrict__ Op)
{
    extern __shared__ char smc[];
    uint2* Ksm = (uint2*)(smc + OFF_K);
    uint2* Vsm = (uint2*)(smc + OFF_V);

    const int qt   = blockIdx.x;
    const int h    = blockIdx.y;
    const int hk   = h >> 2;
    const int tid  = threadIdx.x;
    const int wid  = tid >> 5;
    const int lane = tid & 31;
    const int qr   = lane >> 2;
    const int qc   = lane & 3;
    const int wm   = wid * 32;

    // ---- Q fragments straight into registers (reused for all 32 key tiles) ----
    uint2 qa[2][4][4];   // [mt][ks][a0..a3]
#pragma unroll
    for (int mt = 0; mt < 2; mt++) {
        const uint2* r0 = Qp + (size_t)(qt * 128 + wm + mt * 16 + qr) * (DM / 2) + h * (DH / 2);
        const uint2* r1 = r0 + 8 * (DM / 2);
#pragma unroll
        for (int ks = 0; ks < 4; ks++) {
            qa[mt][ks][0] = r0[ks * 8 + qc];
            qa[mt][ks][1] = r1[ks * 8 + qc];
            qa[mt][ks][2] = r0[ks * 8 + qc + 4];
            qa[mt][ks][3] = r1[ks * 8 + qc + 4];
        }
    }

    float m_i[2][2], l_i[2][2];
#pragma unroll
    for (int mt = 0; mt < 2; mt++)
#pragma unroll
        for (int hf = 0; hf < 2; hf++) { m_i[mt][hf] = -1e30f; l_i[mt][hf] = 0.0f; }

    float acc[2][8][4];
#pragma unroll
    for (int mt = 0; mt < 2; mt++)
#pragma unroll
        for (int nt = 0; nt < 8; nt++)
#pragma unroll
            for (int i = 0; i < 4; i++) acc[mt][nt][i] = 0.0f;

    for (int kt = 0; kt < 32; kt++) {
        __syncthreads();   // all warps done with previous Ksm/Vsm

        // ---- K + V^T fill: pure packed copies ----
        {
            const int row  = tid >> 1;
            const int half = tid & 1;
            const uint2* kg = Kp + (size_t)(kt * 64 + row) * (KVH * DH / 2) + hk * (DH / 2) + half * 16;
            const uint2* vg = Vtp + (size_t)(hk * 64 + row) * (S_LEN / 2) + kt * 32 + half * 16;
            uint2* kd = Ksm + row * AST + half * 16;
            uint2* vd = Vsm + row * AST + half * 16;
#pragma unroll
            for (int j = 0; j < 8; j++) {
                *(uint4*)(kd + 2 * j) = *(const uint4*)(kg + 2 * j);
                *(uint4*)(vd + 2 * j) = *(const uint4*)(vg + 2 * j);
            }
        }
        __syncthreads();

        // ---- S = Q @ K^T (3xBF16; Q from registers) ----
        float s[2][8][4];
#pragma unroll
        for (int mt = 0; mt < 2; mt++)
#pragma unroll
            for (int nt = 0; nt < 8; nt++)
#pragma unroll
                for (int i = 0; i < 4; i++) s[mt][nt][i] = 0.0f;

#pragma unroll
        for (int ks = 0; ks < 4; ks++) {
            uint2 bk[8][2];
#pragma unroll
            for (int nt = 0; nt < 8; nt++) {
                const int o = (nt * 8 + qr) * AST + ks * 8 + qc;
                bk[nt][0] = Ksm[o];
                bk[nt][1] = Ksm[o + 4];
            }
#pragma unroll
            for (int mt = 0; mt < 2; mt++) {
                uint2 a0 = qa[mt][ks][0], a1 = qa[mt][ks][1];
                uint2 a2 = qa[mt][ks][2], a3 = qa[mt][ks][3];
#pragma unroll
                for (int nt = 0; nt < 8; nt++) {
                    mma_bf16(s[mt][nt], a0.x, a1.x, a2.x, a3.x, bk[nt][0].x, bk[nt][1].x);
                    mma_bf16(s[mt][nt], a0.x, a1.x, a2.x, a3.x, bk[nt][0].y, bk[nt][1].y);
                    mma_bf16(s[mt][nt], a0.y, a1.y, a2.y, a3.y, bk[nt][0].x, bk[nt][1].x);
                }
            }
        }

        // ---- online softmax ----
#pragma unroll
        for (int mt = 0; mt < 2; mt++) {
#pragma unroll
            for (int hf = 0; hf < 2; hf++) {
                float mx = -1e30f;
#pragma unroll
                for (int nt = 0; nt < 8; nt++)
                    mx = fmaxf(mx, fmaxf(s[mt][nt][2 * hf], s[mt][nt][2 * hf + 1]));
                mx = fmaxf(mx, __shfl_xor_sync(0xffffffffu, mx, 1));
                mx = fmaxf(mx, __shfl_xor_sync(0xffffffffu, mx, 2));
                float m_new = fmaxf(m_i[mt][hf], mx);
                float alpha = __expf(m_i[mt][hf] - m_new);
                float rs = 0.0f;
#pragma unroll
                for (int nt = 0; nt < 8; nt++) {
                    s[mt][nt][2 * hf]     = __expf(s[mt][nt][2 * hf] - m_new);
                    s[mt][nt][2 * hf + 1] = __expf(s[mt][nt][2 * hf + 1] - m_new);
                    rs += s[mt][nt][2 * hf] + s[mt][nt][2 * hf + 1];
                }
                rs += __shfl_xor_sync(0xffffffffu, rs, 1);
                rs += __shfl_xor_sync(0xffffffffu, rs, 2);
                l_i[mt][hf] = l_i[mt][hf] * alpha + rs;
                m_i[mt][hf] = m_new;
#pragma unroll
                for (int nt = 0; nt < 8; nt++) {
                    acc[mt][nt][2 * hf]     *= alpha;
                    acc[mt][nt][2 * hf + 1] *= alpha;
                }
            }
        }

        // ---- acc += P @ V: P fragments built in registers from s ----
        // A-frag rows {qr, qr+8}, k-block ks keys -> S-tiles nt'=2ks (k lo 8)
        // and nt'=2ks+1 (k hi 8); cols {2qc,2qc+1} are exactly s[..][0..1]/[2..3].
#pragma unroll
        for (int ks = 0; ks < 4; ks++) {
            uint2 bv[8][2];
#pragma unroll
            for (int nt = 0; nt < 8; nt++) {
                const int o = (nt * 8 + qr) * AST + ks * 8 + qc;
                bv[nt][0] = Vsm[o];
                bv[nt][1] = Vsm[o + 4];
            }
#pragma unroll
            for (int mt = 0; mt < 2; mt++) {
                uint32_t ph0, pl0, ph1, pl1, ph2, pl2, ph3, pl3;
                split2(s[mt][2 * ks][0],     s[mt][2 * ks][1],     ph0, pl0);
                split2(s[mt][2 * ks][2],     s[mt][2 * ks][3],     ph1, pl1);
                split2(s[mt][2 * ks + 1][0], s[mt][2 * ks + 1][1], ph2, pl2);
                split2(s[mt][2 * ks + 1][2], s[mt][2 * ks + 1][3], ph3, pl3);
#pragma unroll
                for (int nt = 0; nt < 8; nt++) {
                    mma_bf16(acc[mt][nt], ph0, ph1, ph2, ph3, bv[nt][0].x, bv[nt][1].x);
                    mma_bf16(acc[mt][nt], ph0, ph1, ph2, ph3, bv[nt][0].y, bv[nt][1].y);
                    mma_bf16(acc[mt][nt], pl0, pl1, pl2, pl3, bv[nt][0].x, bv[nt][1].x);
                }
            }
        }
    }

    // ---- epilogue: normalize, pack, store (consumed packed by out-proj) ----
#pragma unroll
    for (int mt = 0; mt < 2; mt++) {
        const float i0 = 1.0f / l_i[mt][0];
        const float i1 = 1.0f / l_i[mt][1];
        const int row = qt * 128 + wm + mt * 16 + qr;
#pragma unroll
        for (int nt = 0; nt < 8; nt++) {
            uint2 o;
            size_t idx0 = (size_t)row * (DM / 2) + h * (DH / 2) + nt * 4 + qc;
            split2(acc[mt][nt][0] * i0, acc[mt][nt][1] * i0, o.x, o.y);
            Op[idx0] = o;
            split2(acc[mt][nt][2] * i1, acc[mt][nt][3] * i1, o.x, o.y);
            Op[idx0 + 8 * (DM / 2)] = o;
        }
    }
}

// ==============================================================================
// launch
// ==============================================================================
extern "C" void kernel_launch(void* const* d_in, const int* in_sizes, int n_in,
                              void* d_out, int out_size)
{
    const float* x     = (const float*)d_in[0];
    const float* W_q   = (const float*)d_in[1];
    const float* b_q   = (const float*)d_in[2];
    const float* W_kv  = (const float*)d_in[3];
    const float* b_kv  = (const float*)d_in[4];
    const float* W_out = (const float*)d_in[5];
    const float* b_out = (const float*)d_in[6];
    float* out = (float*)d_out;

    float *qf, *kvf;
    uint2 *xp, *wqp, *wkvp, *wop, *qp, *kp, *vtp, *ap;
    cudaGetSymbolAddress((void**)&qf,   g_Qf);
    cudaGetSymbolAddress((void**)&kvf,  g_KVf);
    cudaGetSymbolAddress((void**)&xp,   g_xp);
    cudaGetSymbolAddress((void**)&wqp,  g_Wqp);
    cudaGetSymbolAddress((void**)&wkvp, g_Wkvp);
    cudaGetSymbolAddress((void**)&wop,  g_Wop);
    cudaGetSymbolAddress((void**)&qp,   g_Qp);
    cudaGetSymbolAddress((void**)&kp,   g_Kp);
    cudaGetSymbolAddress((void**)&vtp,  g_Vtp);
    cudaGetSymbolAddress((void**)&ap,   g_attnp);

    cudaFuncSetAttribute(flash_attn_p, cudaFuncAttributeMaxDynamicSharedMemorySize, FA_SMEM);
    cudaFuncSetAttribute(tgemm_bf16p, cudaFuncAttributeMaxDynamicSharedMemorySize, TG_SMEM);

    // pack inputs once per launch
    pack_pairs<<<(S_LEN * DM / 2 + 255) / 256, 256>>>((const float2*)x, xp, S_LEN * DM / 2);
    pack_pairs<<<(DM * DM / 2 + 255) / 256, 256>>>((const float2*)W_q, wqp, DM * DM / 2);
    pack_pairs<<<(KV_W * DM / 2 + 255) / 256, 256>>>((const float2*)W_kv, wkvp, KV_W * DM / 2);
    pack_pairs<<<(DM * DM / 2 + 255) / 256, 256>>>((const float2*)W_out, wop, DM * DM / 2);

    // projections (packed operands, fp32 out)
    tgemm_bf16p<<<dim3(DM / 128, S_LEN / 128), 128, TG_SMEM>>>(
        xp, wqp, b_q, qf, S_LEN, DM, DM);
    tgemm_bf16p<<<dim3(KV_W / 128, S_LEN / 128), 128, TG_SMEM>>>(
        xp, wkvp, b_kv, kvf, S_LEN, KV_W, DM);

    // rope+scale+pack Q ; rope+pack K ; transpose+pack V
    ropepack_kernel<<<(S_LEN * QH * 32 + 255) / 256, 256>>>(qf, qp, QH, DM, DM / 2, 0.125f);
    ropepack_kernel<<<(S_LEN * KVH * 32 + 255) / 256, 256>>>(kvf, kp, KVH, KV_W, KVH * DH / 2, 1.0f);
    vtpack_kernel<<<(KVH * DH * S_LEN / 2 + 255) / 256, 256>>>(kvf, vtp);

    // flash attention (packed in/out)
    flash_attn_p<<<dim3(S_LEN / 128, QH), 128, FA_SMEM>>>(qp, kp, vtp, ap);

    // output projection (packed A)
    tgemm_bf16p<<<dim3(DM / 128, S_LEN / 128), 128, TG_SMEM>>>(
        ap, wop, b_out, out, S_LEN, DM, DM);
}

// round 12
// speedup vs baseline: 1.0457x; 1.0457x over previous
#include <cuda_runtime.h>
#include <math.h>
#include <stdint.h>

#define S_LEN 2048
#define DM    2048
#define QH    32
#define KVH   8
#define DH    64
#define KV_W  (2 * KVH * DH)   // 1024

// ---------------- scratch (allocation-free: __device__ globals) ----------------
__device__ float g_Q[S_LEN * DM];            // fp32 Q proj (rope'd in place)
__device__ float g_KV[S_LEN * KV_W];         // fp32 KV proj (K rope'd in place)
__device__ uint2 g_xp[S_LEN * DM / 2];       // packed x
__device__ uint2 g_Wqp[DM * DM / 2];         // packed W_q
__device__ uint2 g_Wkvp[KV_W * DM / 2];      // packed W_kv
__device__ uint2 g_Wop[DM * DM / 2];         // packed W_out
__device__ uint2 g_attnp[S_LEN * DM / 2];    // packed attention output
__device__ float g_freq[32];                 // rope frequency table

// ============================ helpers ====================================
__device__ __forceinline__ uint32_t smem_u32(const void* p) {
    uint32_t a;
    asm("{ .reg .u64 t; cvta.to.shared.u64 t, %1; cvt.u32.u64 %0, t; }" : "=r"(a) : "l"(p));
    return a;
}
#define CP_ASYNC16(dst, src) \
    asm volatile("cp.async.cg.shared.global [%0], [%1], 16;" :: "r"(dst), "l"(src))
#define CP_COMMIT() asm volatile("cp.async.commit_group;" ::: "memory")
#define CP_WAITG(n) asm volatile("cp.async.wait_group %0;" :: "n"(n) : "memory")

__device__ __forceinline__ uint32_t pack_bf16(float f1_hi, float f0_lo) {
    uint32_t d;
    asm("cvt.rn.bf16x2.f32 %0, %1, %2;" : "=r"(d) : "f"(f1_hi), "f"(f0_lo));
    return d;
}
// round-to-nearest hi/lo split of a pair: f = hi + lo, |lo| <= 2^-8 |f|
__device__ __forceinline__ void split2(float f0, float f1, uint32_t& h, uint32_t& l) {
    h = pack_bf16(f1, f0);
    float h0 = __uint_as_float(h << 16);
    float h1 = __uint_as_float(h & 0xFFFF0000u);
    l = pack_bf16(f1 - h1, f0 - h0);
}
__device__ __forceinline__ void mma_bf16(float* d,
                                         uint32_t a0, uint32_t a1, uint32_t a2, uint32_t a3,
                                         uint32_t b0, uint32_t b1) {
    asm volatile(
        "mma.sync.aligned.m16n8k16.row.col.f32.bf16.bf16.f32 "
        "{%0,%1,%2,%3}, {%4,%5,%6,%7}, {%8,%9}, {%0,%1,%2,%3};"
        : "+f"(d[0]), "+f"(d[1]), "+f"(d[2]), "+f"(d[3])
        : "r"(a0), "r"(a1), "r"(a2), "r"(a3), "r"(b0), "r"(b1));
}

// ==============================================================================
// pre-pack: fp32 pairs -> {hi bf16x2, lo bf16x2}
// ==============================================================================
__global__ void pack_pairs(const float2* __restrict__ in, uint2* __restrict__ out, int n2)
{
    int i = blockIdx.x * blockDim.x + threadIdx.x;
    if (i >= n2) return;
    float2 f = in[i];
    uint2 o;
    split2(f.x, f.y, o.x, o.y);
    out[i] = o;
}

// ==============================================================================
// 3xBF16 GEMM, packed operands: C[M,N] = A[M,K] @ B[N,K]^T + bias[N]
// 128x128 CTA tile, BK=32 (16 uint2/row), 128 threads (4 warps, 64x64 tiles).
// smem: 2 stages A[128][20u2]+B[128][20u2]; stride 20 conflict-free
// (idx mod 16 = 4qr+qc distinct per half-warp phase).
// occ 2 (launch_bounds(128,2)) -> ~200 regs, NO spills (R11 lesson).
// Mainloop: pure LDS.64 + HMMA, zero conversion ALU.
// ==============================================================================
#define GST      20                    // uint2 per row (16 data + 4 pad)
#define GTILE_U  (128 * GST)           // 2560 uint2
#define GSTG_U   (2 * GTILE_U)         // A+B per stage
#define TG_SMEM  (2 * GSTG_U * 8)      // 81920 B

__global__ __launch_bounds__(128, 2)
void tgemm_bf16p(const uint2* __restrict__ A, const uint2* __restrict__ B,
                 const float* __restrict__ bias, float* __restrict__ C,
                 int M, int N, int K)
{
    extern __shared__ uint2 smu[];
    const uint32_t smb = smem_u32(smu);

    const int tid  = threadIdx.x;
    const int wid  = tid >> 5;
    const int lane = tid & 31;
    const int qr   = lane >> 2;
    const int qc   = lane & 3;
    const int wm   = (wid & 1) * 64;
    const int wn   = (wid >> 1) * 64;
    const int brow = blockIdx.y * 128;
    const int bcol = blockIdx.x * 128;
    const int ldu  = K >> 1;

    // loader: thread owns one A row and one B row (128 B data per stage each)
    const uint2* Ag = A + (size_t)(brow + tid) * ldu;
    const uint2* Bg = B + (size_t)(bcol + tid) * ldu;
    const uint32_t dst_off = (uint32_t)tid * (GST * 8);

    const int NT = K >> 5;

    auto issue_stage = [&](int kt) {
        const uint32_t da = smb + (uint32_t)((kt & 1) * GSTG_U) * 8 + dst_off;
        const uint32_t db = da + GTILE_U * 8;
        const uint2* sa = Ag + kt * 16;
        const uint2* sb = Bg + kt * 16;
#pragma unroll
        for (int j = 0; j < 8; j++) {
            CP_ASYNC16(da + 16 * j, sa + 2 * j);
            CP_ASYNC16(db + 16 * j, sb + 2 * j);
        }
    };

    float acc[4][8][4];
#pragma unroll
    for (int mt = 0; mt < 4; mt++)
#pragma unroll
        for (int nt = 0; nt < 8; nt++)
#pragma unroll
            for (int i = 0; i < 4; i++) acc[mt][nt][i] = 0.0f;

    issue_stage(0); CP_COMMIT();

    for (int kt = 0; kt < NT; kt++) {
        if (kt + 1 < NT) { issue_stage(kt + 1); CP_COMMIT(); CP_WAITG(1); }
        else             { CP_WAITG(0); }
        __syncthreads();

        const uint2* As = smu + (kt & 1) * GSTG_U;
        const uint2* Bs = As + GTILE_U;

#pragma unroll
        for (int ks = 0; ks < 2; ks++) {
            uint2 bf[8][2];
#pragma unroll
            for (int nt = 0; nt < 8; nt++) {
                const int o = (wn + nt * 8 + qr) * GST + ks * 8 + qc;
                bf[nt][0] = Bs[o];
                bf[nt][1] = Bs[o + 4];
            }
#pragma unroll
            for (int mt = 0; mt < 4; mt++) {
                const int o = (wm + mt * 16 + qr) * GST + ks * 8 + qc;
                uint2 a0 = As[o];
                uint2 a1 = As[o + 8 * GST];
                uint2 a2 = As[o + 4];
                uint2 a3 = As[o + 8 * GST + 4];
#pragma unroll
                for (int nt = 0; nt < 8; nt++) {
                    mma_bf16(acc[mt][nt], a0.x, a1.x, a2.x, a3.x, bf[nt][0].x, bf[nt][1].x);
                    mma_bf16(acc[mt][nt], a0.x, a1.x, a2.x, a3.x, bf[nt][0].y, bf[nt][1].y);
                    mma_bf16(acc[mt][nt], a0.y, a1.y, a2.y, a3.y, bf[nt][0].x, bf[nt][1].x);
                }
            }
        }
        __syncthreads();
    }

#pragma unroll
    for (int mt = 0; mt < 4; mt++) {
        const int row = brow + wm + mt * 16 + qr;
#pragma unroll
        for (int nt = 0; nt < 8; nt++) {
            const int col = bcol + wn + nt * 8 + qc * 2;
            const float b0 = bias[col], b1 = bias[col + 1];
            *(float2*)(C + (size_t)row * N + col) =
                make_float2(acc[mt][nt][0] + b0, acc[mt][nt][1] + b1);
            *(float2*)(C + (size_t)(row + 8) * N + col) =
                make_float2(acc[mt][nt][2] + b0, acc[mt][nt][3] + b1);
        }
    }
}

// ==============================================================================
// RoPE (R8 exact): freq table + in-place fp32 rope
// ==============================================================================
__global__ void freq_kernel()
{
    int j = threadIdx.x;
    if (j < 32) g_freq[j] = (float)pow(10000.0, -(double)j / 32.0);
}

__global__ void rope_kernel(float* __restrict__ X, int H, int rowstride)
{
    int idx = blockIdx.x * blockDim.x + threadIdx.x;
    int total = S_LEN * H * (DH / 2);
    if (idx >= total) return;

    int j = idx & 31;
    int t = idx >> 5;
    int h = t % H;
    int s = t / H;

    float theta = (float)s * g_freq[j];
    float sn, cs;
    sincosf(theta, &sn, &cs);

    float* p = X + (size_t)s * rowstride + h * DH + 2 * j;
    float2 v = *(float2*)p;
    float2 o;
    o.x = v.x * cs - v.y * sn;
    o.y = v.x * sn + v.y * cs;
    *(float2*)p = o;
}

// ==============================================================================
// Flash attention (R8 exact — proven at 1147us): bf16 3-term mma.sync.
// Block = (128 q-rows, head), 128 threads = 4 warps; warp owns 32 rows.
// Q, K, P stored in smem as packed bf16x2 {hi,lo} uint2; V raw fp32.
// Epilogue packs output for the packed out-projection.
// ==============================================================================
#define QST 36        // uint2 stride for QHL/PHL rows
#define KST 36        // uint2 stride for KHL rows
#define VST 68        // float stride for Vs rows
#define OFF_PHL 36864                         // 128*36*8
#define OFF_KHL (OFF_PHL + 36864)             // 73728
#define OFF_VS  (OFF_KHL + 64 * KST * 8)      // 92160
#define FA_SMEM (OFF_VS + 64 * VST * 4)       // 109568

__global__ __launch_bounds__(128, 2)
void flash_attn_bf16(const float* __restrict__ Q, const float* __restrict__ KV,
                     uint2* __restrict__ Op)
{
    extern __shared__ char smc[];
    uint2* QHL = (uint2*)smc;
    uint2* PHL = (uint2*)(smc + OFF_PHL);
    uint2* KHL = (uint2*)(smc + OFF_KHL);
    float* Vs  = (float*)(smc + OFF_VS);

    const int qt   = blockIdx.x;
    const int h    = blockIdx.y;
    const int hk   = h >> 2;
    const int tid  = threadIdx.x;
    const int wid  = tid >> 5;
    const int lane = tid & 31;
    const int qr   = lane >> 2;
    const int qc   = lane & 3;
    const int wm   = wid * 32;

    // ---- Q fill: scale by 1/8, split hi/lo, pack ----
    {
        const float* src = Q + (size_t)(qt * 128 + tid) * DM + h * DH;
        uint2* dst = QHL + tid * QST;
#pragma unroll
        for (int j = 0; j < 16; j++) {
            float4 v = *(const float4*)(src + 4 * j);
            uint32_t h01, l01, h23, l23;
            split2(v.x * 0.125f, v.y * 0.125f, h01, l01);
            split2(v.z * 0.125f, v.w * 0.125f, h23, l23);
            *(uint4*)(dst + 2 * j) = make_uint4(h01, l01, h23, l23);
        }
    }

    float m_i[2][2], l_i[2][2];
#pragma unroll
    for (int mt = 0; mt < 2; mt++)
#pragma unroll
        for (int hf = 0; hf < 2; hf++) { m_i[mt][hf] = -1e30f; l_i[mt][hf] = 0.0f; }

    float acc[2][8][4];
#pragma unroll
    for (int mt = 0; mt < 2; mt++)
#pragma unroll
        for (int nt = 0; nt < 8; nt++)
#pragma unroll
            for (int i = 0; i < 4; i++) acc[mt][nt][i] = 0.0f;

    for (int kt = 0; kt < 32; kt++) {
        __syncthreads();

        // ---- K fill (packed bf16 hi/lo) + V fill (raw fp32) ----
        {
            const int row = tid >> 1;
            const int db  = (tid & 1) * 32;
            const float* ksrc = KV + (size_t)(kt * 64 + row) * KV_W + hk * DH + db;
            const float* vsrc = ksrc + KVH * DH;
            uint2* kd = KHL + row * KST + (db >> 1);
            float* vd = Vs + row * VST + db;
#pragma unroll
            for (int j = 0; j < 8; j++) {
                float4 v = *(const float4*)(ksrc + 4 * j);
                uint32_t h01, l01, h23, l23;
                split2(v.x, v.y, h01, l01);
                split2(v.z, v.w, h23, l23);
                *(uint4*)(kd + 2 * j) = make_uint4(h01, l01, h23, l23);
                *(float4*)(vd + 4 * j) = *(const float4*)(vsrc + 4 * j);
            }
        }
        __syncthreads();

        // ---- S = Q @ K^T (3xBF16) ----
        float s[2][8][4];
#pragma unroll
        for (int mt = 0; mt < 2; mt++)
#pragma unroll
            for (int nt = 0; nt < 8; nt++)
#pragma unroll
                for (int i = 0; i < 4; i++) s[mt][nt][i] = 0.0f;

#pragma unroll
        for (int ks = 0; ks < 4; ks++) {
            uint2 bk[8][2];
#pragma unroll
            for (int nt = 0; nt < 8; nt++) {
                const int kb = (nt * 8 + qr) * KST + ks * 8 + qc;
                bk[nt][0] = KHL[kb];
                bk[nt][1] = KHL[kb + 4];
            }
#pragma unroll
            for (int mt = 0; mt < 2; mt++) {
                const int qb = (wm + mt * 16 + qr) * QST + ks * 8 + qc;
                uint2 a0 = QHL[qb];
                uint2 a1 = QHL[qb + 8 * QST];
                uint2 a2 = QHL[qb + 4];
                uint2 a3 = QHL[qb + 8 * QST + 4];
#pragma unroll
                for (int nt = 0; nt < 8; nt++) {
                    mma_bf16(s[mt][nt], a0.x, a1.x, a2.x, a3.x, bk[nt][0].x, bk[nt][1].x);
                    mma_bf16(s[mt][nt], a0.x, a1.x, a2.x, a3.x, bk[nt][0].y, bk[nt][1].y);
                    mma_bf16(s[mt][nt], a0.y, a1.y, a2.y, a3.y, bk[nt][0].x, bk[nt][1].x);
                }
            }
        }

        // ---- online softmax ----
#pragma unroll
        for (int mt = 0; mt < 2; mt++) {
#pragma unroll
            for (int hf = 0; hf < 2; hf++) {
                float mx = -1e30f;
#pragma unroll
                for (int nt = 0; nt < 8; nt++)
                    mx = fmaxf(mx, fmaxf(s[mt][nt][2 * hf], s[mt][nt][2 * hf + 1]));
                mx = fmaxf(mx, __shfl_xor_sync(0xffffffffu, mx, 1));
                mx = fmaxf(mx, __shfl_xor_sync(0xffffffffu, mx, 2));
                float m_new = fmaxf(m_i[mt][hf], mx);
                float alpha = __expf(m_i[mt][hf] - m_new);
                float rs = 0.0f;
#pragma unroll
                for (int nt = 0; nt < 8; nt++) {
                    s[mt][nt][2 * hf]     = __expf(s[mt][nt][2 * hf] - m_new);
                    s[mt][nt][2 * hf + 1] = __expf(s[mt][nt][2 * hf + 1] - m_new);
                    rs += s[mt][nt][2 * hf] + s[mt][nt][2 * hf + 1];
                }
                rs += __shfl_xor_sync(0xffffffffu, rs, 1);
                rs += __shfl_xor_sync(0xffffffffu, rs, 2);
                l_i[mt][hf] = l_i[mt][hf] * alpha + rs;
                m_i[mt][hf] = m_new;
#pragma unroll
                for (int nt = 0; nt < 8; nt++) {
                    acc[mt][nt][2 * hf]     *= alpha;
                    acc[mt][nt][2 * hf + 1] *= alpha;
                }
            }
        }

        // ---- write P packed (warp-private rows) ----
#pragma unroll
        for (int mt = 0; mt < 2; mt++) {
            const int r0 = (wm + mt * 16 + qr) * QST;
#pragma unroll
            for (int nt = 0; nt < 8; nt++) {
                uint2 o;
                split2(s[mt][nt][0], s[mt][nt][1], o.x, o.y);
                PHL[r0 + nt * 4 + qc] = o;
                split2(s[mt][nt][2], s[mt][nt][3], o.x, o.y);
                PHL[r0 + 8 * QST + nt * 4 + qc] = o;
            }
        }
        __syncwarp();

        // ---- acc += P @ V (3xBF16); V converted in-loop from fp32 columns ----
#pragma unroll
        for (int ks = 0; ks < 4; ks++) {
            uint32_t vh[8][2], vl[8][2];
#pragma unroll
            for (int nt = 0; nt < 8; nt++) {
                const int n  = nt * 8 + qr;
                const int k0 = ks * 16 + 2 * qc;
                float f0 = Vs[k0 * VST + n];
                float f1 = Vs[(k0 + 1) * VST + n];
                split2(f0, f1, vh[nt][0], vl[nt][0]);
                float f2 = Vs[(k0 + 8) * VST + n];
                float f3 = Vs[(k0 + 9) * VST + n];
                split2(f2, f3, vh[nt][1], vl[nt][1]);
            }
#pragma unroll
            for (int mt = 0; mt < 2; mt++) {
                const int pb = (wm + mt * 16 + qr) * QST + ks * 8 + qc;
                uint2 p0 = PHL[pb];
                uint2 p1 = PHL[pb + 8 * QST];
                uint2 p2 = PHL[pb + 4];
                uint2 p3 = PHL[pb + 8 * QST + 4];
#pragma unroll
                for (int nt = 0; nt < 8; nt++) {
                    mma_bf16(acc[mt][nt], p0.x, p1.x, p2.x, p3.x, vh[nt][0], vh[nt][1]);
                    mma_bf16(acc[mt][nt], p0.x, p1.x, p2.x, p3.x, vl[nt][0], vl[nt][1]);
                    mma_bf16(acc[mt][nt], p0.y, p1.y, p2.y, p3.y, vh[nt][0], vh[nt][1]);
                }
            }
        }
    }

    // ---- epilogue: normalize, pack, store (consumed packed by out-proj) ----
#pragma unroll
    for (int mt = 0; mt < 2; mt++) {
        const float i0 = 1.0f / l_i[mt][0];
        const float i1 = 1.0f / l_i[mt][1];
        const int row = qt * 128 + wm + mt * 16 + qr;
#pragma unroll
        for (int nt = 0; nt < 8; nt++) {
            uint2 o;
            size_t idx0 = (size_t)row * (DM / 2) + h * (DH / 2) + nt * 4 + qc;
            split2(acc[mt][nt][0] * i0, acc[mt][nt][1] * i0, o.x, o.y);
            Op[idx0] = o;
            split2(acc[mt][nt][2] * i1, acc[mt][nt][3] * i1, o.x, o.y);
            Op[idx0 + 8 * (DM / 2)] = o;
        }
    }
}

// ==============================================================================
// launch  (GEMM-KV at index 5 -> ncu -s 5 -c 1 captures the new GEMM)
// ==============================================================================
extern "C" void kernel_launch(void* const* d_in, const int* in_sizes, int n_in,
                              void* d_out, int out_size)
{
    const float* x     = (const float*)d_in[0];
    const float* W_q   = (const float*)d_in[1];
    const float* b_q   = (const float*)d_in[2];
    const float* W_kv  = (const float*)d_in[3];
    const float* b_kv  = (const float*)d_in[4];
    const float* W_out = (const float*)d_in[5];
    const float* b_out = (const float*)d_in[6];
    float* out = (float*)d_out;

    float *qf, *kvf;
    uint2 *xp, *wqp, *wkvp, *wop, *ap;
    cudaGetSymbolAddress((void**)&qf,   g_Q);
    cudaGetSymbolAddress((void**)&kvf,  g_KV);
    cudaGetSymbolAddress((void**)&xp,   g_xp);
    cudaGetSymbolAddress((void**)&wqp,  g_Wqp);
    cudaGetSymbolAddress((void**)&wkvp, g_Wkvp);
    cudaGetSymbolAddress((void**)&wop,  g_Wop);
    cudaGetSymbolAddress((void**)&ap,   g_attnp);

    cudaFuncSetAttribute(flash_attn_bf16, cudaFuncAttributeMaxDynamicSharedMemorySize, FA_SMEM);
    cudaFuncSetAttribute(tgemm_bf16p, cudaFuncAttributeMaxDynamicSharedMemorySize, TG_SMEM);

    // 0-3: pack inputs once per launch
    pack_pairs<<<(S_LEN * DM / 2 + 255) / 256, 256>>>((const float2*)x, xp, S_LEN * DM / 2);
    pack_pairs<<<(DM * DM / 2 + 255) / 256, 256>>>((const float2*)W_q, wqp, DM * DM / 2);
    pack_pairs<<<(KV_W * DM / 2 + 255) / 256, 256>>>((const float2*)W_kv, wkvp, KV_W * DM / 2);
    pack_pairs<<<(DM * DM / 2 + 255) / 256, 256>>>((const float2*)W_out, wop, DM * DM / 2);

    // 4: Q projection ; 5: KV projection (ncu captures 5)
    tgemm_bf16p<<<dim3(DM / 128, S_LEN / 128), 128, TG_SMEM>>>(
        xp, wqp, b_q, qf, S_LEN, DM, DM);
    tgemm_bf16p<<<dim3(KV_W / 128, S_LEN / 128), 128, TG_SMEM>>>(
        xp, wkvp, b_kv, kvf, S_LEN, KV_W, DM);

    // 6-8: rope (in place, fp32)
    freq_kernel<<<1, 32>>>();
    rope_kernel<<<(S_LEN * QH * 32 + 255) / 256, 256>>>(qf, QH, DM);
    rope_kernel<<<(S_LEN * KVH * 32 + 255) / 256, 256>>>(kvf, KVH, KV_W);

    // 9: flash attention (R8 exact; packed output)
    flash_attn_bf16<<<dim3(S_LEN / 128, QH), 128, FA_SMEM>>>(qf, kvf, ap);

    // 10: output projection (packed A)
    tgemm_bf16p<<<dim3(DM / 128, S_LEN / 128), 128, TG_SMEM>>>(
        ap, wop, b_out, out, S_LEN, DM, DM);
}

// round 13
// speedup vs baseline: 1.2793x; 1.2234x over previous
#include <cuda_runtime.h>
#include <math.h>
#include <stdint.h>

#define S_LEN 2048
#define DM    2048
#define QH    32
#define KVH   8
#define DH    64
#define KV_W  (2 * KVH * DH)   // 1024

// ---------------- scratch (allocation-free: __device__ globals) ----------------
__device__ float g_Q[S_LEN * DM];        // 16 MB fp32 Q proj (rope'd in place)
__device__ float g_KV[S_LEN * KV_W];     //  8 MB fp32 KV proj (K rope'd in place)
__device__ float g_attn[S_LEN * DM];     // 16 MB fp32 attention output
__device__ float g_freq[32];             // rope frequency table

// ============================ helpers ====================================
__device__ __forceinline__ uint32_t smem_u32(const void* p) {
    uint32_t a;
    asm("{ .reg .u64 t; cvta.to.shared.u64 t, %1; cvt.u32.u64 %0, t; }" : "=r"(a) : "l"(p));
    return a;
}
#define CP_ASYNC16(dst, src) \
    asm volatile("cp.async.cg.shared.global [%0], [%1], 16;" :: "r"(dst), "l"(src))
#define CP_COMMIT() asm volatile("cp.async.commit_group;" ::: "memory")
#define CP_WAIT1()  asm volatile("cp.async.wait_group 1;" ::: "memory")
#define CP_WAIT0()  asm volatile("cp.async.wait_group 0;" ::: "memory")

__device__ __forceinline__ uint32_t pack_bf16(float f1_hi, float f0_lo) {
    uint32_t d;
    asm("cvt.rn.bf16x2.f32 %0, %1, %2;" : "=r"(d) : "f"(f1_hi), "f"(f0_lo));
    return d;
}
// round-to-nearest hi/lo split of a pair: f = hi + lo, |lo| <= 2^-8 |f|
__device__ __forceinline__ void split2(float f0, float f1, uint32_t& h, uint32_t& l) {
    h = pack_bf16(f1, f0);
    float h0 = __uint_as_float(h << 16);
    float h1 = __uint_as_float(h & 0xFFFF0000u);
    l = pack_bf16(f1 - h1, f0 - h0);
}
__device__ __forceinline__ void mma_bf16(float* d,
                                         uint32_t a0, uint32_t a1, uint32_t a2, uint32_t a3,
                                         uint32_t b0, uint32_t b1) {
    asm volatile(
        "mma.sync.aligned.m16n8k16.row.col.f32.bf16.bf16.f32 "
        "{%0,%1,%2,%3}, {%4,%5,%6,%7}, {%8,%9}, {%0,%1,%2,%3};"
        : "+f"(d[0]), "+f"(d[1]), "+f"(d[2]), "+f"(d[3])
        : "r"(a0), "r"(a1), "r"(a2), "r"(a3), "r"(b0), "r"(b1));
}

// ==============================================================================
// 3xBF16 GEMM via mma.sync + cp.async  (EXACT R8 version — proven 1147us)
// 128x128 CTA tile, BK=16, 128 threads (4 warps, 64x64 warp tiles).
// ==============================================================================
#define BK     16
#define SSTR   24
#define ST_F   (128 * SSTR)
#define STG_F  (2 * ST_F)
#define NSTG   3
#define TG_SMEM (NSTG * STG_F * 4)  // 73728 B

__global__ __launch_bounds__(128, 2)
void tgemm_bf16_nt_bias(const float* __restrict__ A, const float* __restrict__ B,
                        const float* __restrict__ bias, float* __restrict__ C,
                        int M, int N, int K)
{
    extern __shared__ float sm[];
    const uint32_t smb = smem_u32(sm);

    const int tid  = threadIdx.x;
    const int wid  = tid >> 5;
    const int lane = tid & 31;
    const int qr   = lane >> 2;
    const int qc   = lane & 3;
    const int wm   = (wid & 1) * 64;
    const int wn   = (wid >> 1) * 64;
    const int brow = blockIdx.y * 128;
    const int bcol = blockIdx.x * 128;

    const float* Ag = A + (size_t)(brow + tid) * K;
    const float* Bg = B + (size_t)(bcol + tid) * K;
    const uint32_t dst_off = (uint32_t)(tid * SSTR) * 4;

    const int NT = K / BK;

    auto issue_stage = [&](int kt) {
        const uint32_t da = smb + (uint32_t)((kt % NSTG) * STG_F) * 4 + dst_off;
        const uint32_t db = da + ST_F * 4;
        const float* sa = Ag + kt * BK;
        const float* sb = Bg + kt * BK;
#pragma unroll
        for (int j = 0; j < 4; j++) {
            CP_ASYNC16(da + 16 * j, sa + 4 * j);
            CP_ASYNC16(db + 16 * j, sb + 4 * j);
        }
    };

    float acc[4][8][4];
#pragma unroll
    for (int mt = 0; mt < 4; mt++)
#pragma unroll
        for (int nt = 0; nt < 8; nt++)
#pragma unroll
            for (int i = 0; i < 4; i++) acc[mt][nt][i] = 0.0f;

    issue_stage(0); CP_COMMIT();
    issue_stage(1); CP_COMMIT();

    for (int kt = 0; kt < NT; kt++) {
        CP_WAIT1();
        __syncthreads();

        if (kt + 2 < NT) issue_stage(kt + 2);
        CP_COMMIT();

        const float* As = sm + (kt % NSTG) * STG_F;
        const float* Bs = As + ST_F;

        uint32_t bh[8][2], bl[8][2];
#pragma unroll
        for (int nt = 0; nt < 8; nt++) {
            const int off = (wn + nt * 8 + qr) * SSTR + 2 * qc;
            float2 f = *(const float2*)&Bs[off];
            float2 g = *(const float2*)&Bs[off + 8];
            split2(f.x, f.y, bh[nt][0], bl[nt][0]);
            split2(g.x, g.y, bh[nt][1], bl[nt][1]);
        }
#pragma unroll
        for (int mt = 0; mt < 4; mt++) {
            const int off = (wm + mt * 16 + qr) * SSTR + 2 * qc;
            float2 f0 = *(const float2*)&As[off];
            float2 f1 = *(const float2*)&As[off + 8 * SSTR];
            float2 f2 = *(const float2*)&As[off + 8];
            float2 f3 = *(const float2*)&As[off + 8 * SSTR + 8];
            uint32_t ah0, ah1, ah2, ah3, al0, al1, al2, al3;
            split2(f0.x, f0.y, ah0, al0);
            split2(f1.x, f1.y, ah1, al1);
            split2(f2.x, f2.y, ah2, al2);
            split2(f3.x, f3.y, ah3, al3);
#pragma unroll
            for (int nt = 0; nt < 8; nt++) {
                mma_bf16(acc[mt][nt], ah0, ah1, ah2, ah3, bh[nt][0], bh[nt][1]);
                mma_bf16(acc[mt][nt], ah0, ah1, ah2, ah3, bl[nt][0], bl[nt][1]);
                mma_bf16(acc[mt][nt], al0, al1, al2, al3, bh[nt][0], bh[nt][1]);
            }
        }
        __syncthreads();
    }

#pragma unroll
    for (int mt = 0; mt < 4; mt++) {
        const int row = brow + wm + mt * 16 + qr;
#pragma unroll
        for (int nt = 0; nt < 8; nt++) {
            const int col = bcol + wn + nt * 8 + qc * 2;
            const float b0 = bias[col], b1 = bias[col + 1];
            *(float2*)(C + (size_t)row * N + col) =
                make_float2(acc[mt][nt][0] + b0, acc[mt][nt][1] + b1);
            *(float2*)(C + (size_t)(row + 8) * N + col) =
                make_float2(acc[mt][nt][2] + b0, acc[mt][nt][3] + b1);
        }
    }
}

// ==============================================================================
// RoPE (R8 exact)
// ==============================================================================
__global__ void freq_kernel()
{
    int j = threadIdx.x;
    if (j < 32) g_freq[j] = (float)pow(10000.0, -(double)j / 32.0);
}

__global__ void rope_kernel(float* __restrict__ X, int H, int rowstride)
{
    int idx = blockIdx.x * blockDim.x + threadIdx.x;
    int total = S_LEN * H * (DH / 2);
    if (idx >= total) return;

    int j = idx & 31;
    int t = idx >> 5;
    int h = t % H;
    int s = t / H;

    float theta = (float)s * g_freq[j];
    float sn, cs;
    sincosf(theta, &sn, &cs);

    float* p = X + (size_t)s * rowstride + h * DH + 2 * j;
    float2 v = *(float2*)p;
    float2 o;
    o.x = v.x * cs - v.y * sn;
    o.y = v.x * sn + v.y * cs;
    *(float2*)p = o;
}

// ==============================================================================
// Flash attention: R8 numerics, pipelined fills.
//  - V: cp.async double-buffer (raw fp32), issued one tile ahead
//  - K: register prefetch one tile ahead, split+STS only in fill phase
//  - P: fragments built in registers (R11-proven mapping), no smem round-trip
// Block = (128 q-rows, head), 128 threads = 4 warps; warp owns 32 rows.
// smem: QHL 36864 + KHL 18432 + V double 34816 = 90112 B -> occ 2.
// ==============================================================================
#define QST 36        // uint2 stride for QHL rows
#define KST 36        // uint2 stride for KHL rows
#define VST 68        // float stride for V rows
#define VBUF_F (64 * VST)                     // 4352 floats per V buffer
#define OFF_KHL 36864                         // after QHL (128*36*8)
#define OFF_VS  (OFF_KHL + 64 * KST * 8)      // 36864 + 18432 = 55296
#define FA_SMEM (OFF_VS + 2 * VBUF_F * 4)     // 55296 + 34816 = 90112

__global__ __launch_bounds__(128, 2)
void flash_attn_bf16(const float* __restrict__ Q, const float* __restrict__ KV,
                     float* __restrict__ O)
{
    extern __shared__ char smc[];
    const uint32_t smb = smem_u32(smc);
    uint2* QHL = (uint2*)smc;
    uint2* KHL = (uint2*)(smc + OFF_KHL);
    float* Vs  = (float*)(smc + OFF_VS);

    const int qt   = blockIdx.x;
    const int h    = blockIdx.y;
    const int hk   = h >> 2;
    const int tid  = threadIdx.x;
    const int wid  = tid >> 5;
    const int lane = tid & 31;
    const int qr   = lane >> 2;
    const int qc   = lane & 3;
    const int wm   = wid * 32;

    // loader mapping for K/V tiles: thread owns key-row (tid>>1), 32-dim half
    const int lrow  = tid >> 1;
    const int lhalf = (tid & 1) * 32;
    const float* kbase = KV + (size_t)lrow * KV_W + hk * DH + lhalf;          // + kt*64*KV_W
    const float* vbase = kbase + KVH * DH;
    uint2* kdst = KHL + lrow * KST + (lhalf >> 1);
    const uint32_t vdst_off = smb + OFF_VS + (uint32_t)(lrow * VST + lhalf) * 4;

    auto issue_V = [&](int kt) {
        const float* src = vbase + (size_t)(kt * 64) * KV_W;
        uint32_t dst = vdst_off + (uint32_t)((kt & 1) * VBUF_F) * 4;
#pragma unroll
        for (int j = 0; j < 8; j++) CP_ASYNC16(dst + 16 * j, src + 4 * j);
    };

    // ---- Q fill: scale by 1/8, split hi/lo, pack (R8 exact) ----
    {
        const float* src = Q + (size_t)(qt * 128 + tid) * DM + h * DH;
        uint2* dst = QHL + tid * QST;
#pragma unroll
        for (int j = 0; j < 16; j++) {
            float4 v = *(const float4*)(src + 4 * j);
            uint32_t h01, l01, h23, l23;
            split2(v.x * 0.125f, v.y * 0.125f, h01, l01);
            split2(v.z * 0.125f, v.w * 0.125f, h23, l23);
            *(uint4*)(dst + 2 * j) = make_uint4(h01, l01, h23, l23);
        }
    }

    // ---- prologue: V(0) in flight, K(0) in registers ----
    issue_V(0); CP_COMMIT();
    float4 kreg[8];
    {
        const float* src = kbase;
#pragma unroll
        for (int j = 0; j < 8; j++) kreg[j] = *(const float4*)(src + 4 * j);
    }

    float m_i[2][2], l_i[2][2];
#pragma unroll
    for (int mt = 0; mt < 2; mt++)
#pragma unroll
        for (int hf = 0; hf < 2; hf++) { m_i[mt][hf] = -1e30f; l_i[mt][hf] = 0.0f; }

    float acc[2][8][4];
#pragma unroll
    for (int mt = 0; mt < 2; mt++)
#pragma unroll
        for (int nt = 0; nt < 8; nt++)
#pragma unroll
            for (int i = 0; i < 4; i++) acc[mt][nt][i] = 0.0f;

    for (int kt = 0; kt < 32; kt++) {
        __syncthreads();   // all warps done reading KHL(kt-1) and V buf (kt+1)&1

        // ---- K fill from prefetched registers: split + STS only ----
#pragma unroll
        for (int j = 0; j < 8; j++) {
            uint32_t h01, l01, h23, l23;
            split2(kreg[j].x, kreg[j].y, h01, l01);
            split2(kreg[j].z, kreg[j].w, h23, l23);
            *(uint4*)(kdst + 2 * j) = make_uint4(h01, l01, h23, l23);
        }
        // prefetch K(kt+1) into registers (latency covered by compute below)
        if (kt + 1 < 32) {
            const float* src = kbase + (size_t)((kt + 1) * 64) * KV_W;
#pragma unroll
            for (int j = 0; j < 8; j++) kreg[j] = *(const float4*)(src + 4 * j);
        }
        // V pipeline: issue kt+1, wait for kt
        if (kt + 1 < 32) { issue_V(kt + 1); CP_COMMIT(); CP_WAIT1(); }
        else             { CP_WAIT0(); }
        __syncthreads();

        const float* Vcur = Vs + (kt & 1) * VBUF_F;

        // ---- S = Q @ K^T (3xBF16; R8 exact) ----
        float s[2][8][4];
#pragma unroll
        for (int mt = 0; mt < 2; mt++)
#pragma unroll
            for (int nt = 0; nt < 8; nt++)
#pragma unroll
                for (int i = 0; i < 4; i++) s[mt][nt][i] = 0.0f;

#pragma unroll
        for (int ks = 0; ks < 4; ks++) {
            uint2 bk[8][2];
#pragma unroll
            for (int nt = 0; nt < 8; nt++) {
                const int kb = (nt * 8 + qr) * KST + ks * 8 + qc;
                bk[nt][0] = KHL[kb];
                bk[nt][1] = KHL[kb + 4];
            }
#pragma unroll
            for (int mt = 0; mt < 2; mt++) {
                const int qb = (wm + mt * 16 + qr) * QST + ks * 8 + qc;
                uint2 a0 = QHL[qb];
                uint2 a1 = QHL[qb + 8 * QST];
                uint2 a2 = QHL[qb + 4];
                uint2 a3 = QHL[qb + 8 * QST + 4];
#pragma unroll
                for (int nt = 0; nt < 8; nt++) {
                    mma_bf16(s[mt][nt], a0.x, a1.x, a2.x, a3.x, bk[nt][0].x, bk[nt][1].x);
                    mma_bf16(s[mt][nt], a0.x, a1.x, a2.x, a3.x, bk[nt][0].y, bk[nt][1].y);
                    mma_bf16(s[mt][nt], a0.y, a1.y, a2.y, a3.y, bk[nt][0].x, bk[nt][1].x);
                }
            }
        }

        // ---- online softmax (R8 exact) ----
#pragma unroll
        for (int mt = 0; mt < 2; mt++) {
#pragma unroll
            for (int hf = 0; hf < 2; hf++) {
                float mx = -1e30f;
#pragma unroll
                for (int nt = 0; nt < 8; nt++)
                    mx = fmaxf(mx, fmaxf(s[mt][nt][2 * hf], s[mt][nt][2 * hf + 1]));
                mx = fmaxf(mx, __shfl_xor_sync(0xffffffffu, mx, 1));
                mx = fmaxf(mx, __shfl_xor_sync(0xffffffffu, mx, 2));
                float m_new = fmaxf(m_i[mt][hf], mx);
                float alpha = __expf(m_i[mt][hf] - m_new);
                float rs = 0.0f;
#pragma unroll
                for (int nt = 0; nt < 8; nt++) {
                    s[mt][nt][2 * hf]     = __expf(s[mt][nt][2 * hf] - m_new);
                    s[mt][nt][2 * hf + 1] = __expf(s[mt][nt][2 * hf + 1] - m_new);
                    rs += s[mt][nt][2 * hf] + s[mt][nt][2 * hf + 1];
                }
                rs += __shfl_xor_sync(0xffffffffu, rs, 1);
                rs += __shfl_xor_sync(0xffffffffu, rs, 2);
                l_i[mt][hf] = l_i[mt][hf] * alpha + rs;
                m_i[mt][hf] = m_new;
#pragma unroll
                for (int nt = 0; nt < 8; nt++) {
                    acc[mt][nt][2 * hf]     *= alpha;
                    acc[mt][nt][2 * hf + 1] *= alpha;
                }
            }
        }

        // ---- acc += P @ V: P frags in registers (R11-proven mapping),
        //      V split in-loop from fp32 columns (R8 exact values) ----
#pragma unroll
        for (int ks = 0; ks < 4; ks++) {
            uint32_t vh[8][2], vl[8][2];
#pragma unroll
            for (int nt = 0; nt < 8; nt++) {
                const int n  = nt * 8 + qr;
                const int k0 = ks * 16 + 2 * qc;
                float f0 = Vcur[k0 * VST + n];
                float f1 = Vcur[(k0 + 1) * VST + n];
                split2(f0, f1, vh[nt][0], vl[nt][0]);
                float f2 = Vcur[(k0 + 8) * VST + n];
                float f3 = Vcur[(k0 + 9) * VST + n];
                split2(f2, f3, vh[nt][1], vl[nt][1]);
            }
#pragma unroll
            for (int mt = 0; mt < 2; mt++) {
                uint32_t ph0, pl0, ph1, pl1, ph2, pl2, ph3, pl3;
                split2(s[mt][2 * ks][0],     s[mt][2 * ks][1],     ph0, pl0);
                split2(s[mt][2 * ks][2],     s[mt][2 * ks][3],     ph1, pl1);
                split2(s[mt][2 * ks + 1][0], s[mt][2 * ks + 1][1], ph2, pl2);
                split2(s[mt][2 * ks + 1][2], s[mt][2 * ks + 1][3], ph3, pl3);
#pragma unroll
                for (int nt = 0; nt < 8; nt++) {
                    mma_bf16(acc[mt][nt], ph0, ph1, ph2, ph3, vh[nt][0], vh[nt][1]);
                    mma_bf16(acc[mt][nt], ph0, ph1, ph2, ph3, vl[nt][0], vl[nt][1]);
                    mma_bf16(acc[mt][nt], pl0, pl1, pl2, pl3, vh[nt][0], vh[nt][1]);
                }
            }
        }
    }

    // ---- epilogue: normalize, store fp32 (R8 exact) ----
#pragma unroll
    for (int mt = 0; mt < 2; mt++) {
        const float i0 = 1.0f / l_i[mt][0];
        const float i1 = 1.0f / l_i[mt][1];
        float* d0 = O + (size_t)(qt * 128 + wm + mt * 16 + qr) * DM + h * DH;
        float* d1 = d0 + (size_t)8 * DM;
#pragma unroll
        for (int nt = 0; nt < 8; nt++) {
            *(float2*)(d0 + nt * 8 + 2 * qc) =
                make_float2(acc[mt][nt][0] * i0, acc[mt][nt][1] * i0);
            *(float2*)(d1 + nt * 8 + 2 * qc) =
                make_float2(acc[mt][nt][2] * i1, acc[mt][nt][3] * i1);
        }
    }
}

// ==============================================================================
// launch (R8 exact structure)
// ==============================================================================
extern "C" void kernel_launch(void* const* d_in, const int* in_sizes, int n_in,
                              void* d_out, int out_size)
{
    const float* x     = (const float*)d_in[0];
    const float* W_q   = (const float*)d_in[1];
    const float* b_q   = (const float*)d_in[2];
    const float* W_kv  = (const float*)d_in[3];
    const float* b_kv  = (const float*)d_in[4];
    const float* W_out = (const float*)d_in[5];
    const float* b_out = (const float*)d_in[6];
    float* out = (float*)d_out;

    float *qbuf, *kvbuf, *abuf;
    cudaGetSymbolAddress((void**)&qbuf, g_Q);
    cudaGetSymbolAddress((void**)&kvbuf, g_KV);
    cudaGetSymbolAddress((void**)&abuf, g_attn);

    cudaFuncSetAttribute(flash_attn_bf16, cudaFuncAttributeMaxDynamicSharedMemorySize, FA_SMEM);
    cudaFuncSetAttribute(tgemm_bf16_nt_bias, cudaFuncAttributeMaxDynamicSharedMemorySize, TG_SMEM);

    freq_kernel<<<1, 32>>>();

    // Q projection: [2048,2048]
    tgemm_bf16_nt_bias<<<dim3(DM / 128, S_LEN / 128), 128, TG_SMEM>>>(
        x, W_q, b_q, qbuf, S_LEN, DM, DM);

    // KV projection: [2048,1024]
    tgemm_bf16_nt_bias<<<dim3(KV_W / 128, S_LEN / 128), 128, TG_SMEM>>>(
        x, W_kv, b_kv, kvbuf, S_LEN, KV_W, DM);

    // RoPE
    rope_kernel<<<(S_LEN * QH * 32 + 255) / 256, 256>>>(qbuf, QH, DM);
    rope_kernel<<<(S_LEN * KVH * 32 + 255) / 256, 256>>>(kvbuf, KVH, KV_W);

    // Flash attention (pipelined fills, R8 numerics)
    flash_attn_bf16<<<dim3(S_LEN / 128, QH), 128, FA_SMEM>>>(qbuf, kvbuf, abuf);

    // Output projection: [2048,2048]
    tgemm_bf16_nt_bias<<<dim3(DM / 128, S_LEN / 128), 128, TG_SMEM>>>(
        abuf, W_out, b_out, out, S_LEN, DM, DM);
}